// round 4
// baseline (speedup 1.0000x reference)
#include <cuda_runtime.h>
#include <math_constants.h>

// img (1,200,200,512) f32 NHWC, rois (1,128,4) f32 (x,y,w,h), pool 7x7
// out (1,128,7,7,512) f32.
#define IMG_H 200
#define IMG_W 200
#define IMG_C 512
#define POOLP 7
#define NROIS 128
#define NBINS (POOLP * POOLP)   // 49
#define C4    (IMG_C / 4)       // 128 float4 per full channel record

#define TW 10
#define TH 10
#define NTX (IMG_W / TW)        // 20 (exact)
#define NTY (IMG_H / TH)        // 20 (exact)

// ---- device scratch (static globals: allocation-free) --------------------
// Bin boundaries per ROI (computed once per launch, bit-identical everywhere).
__device__ int  g_bx[NROIS][8];
__device__ int  g_by[NROIS][8];
__device__ int4 g_bbox[NROIS];           // (bx0, bx7, by0, by7)
// Partial maxima: [roi][jy][ix][sy][sx][512ch]. A bin is <=10px wide/tall
// (w,h < 64 => step < 9.15), tile is 10 => a bin spans <=2 tiles per axis.
__device__ float4 g_partial[(size_t)NROIS * NBINS * 4 * C4];   // 51.4 MB

// ---- kernel 1: bin boundaries -------------------------------------------
// Must match JAX f32 op order exactly: step = w/7; b[k] = int(x + k*step),
// mul then add, NO fma contraction.
__global__ __launch_bounds__(NROIS) void prep_kernel(const float* __restrict__ rois)
{
    int r = threadIdx.x;
    float rx = rois[r * 4 + 0], ry = rois[r * 4 + 1];
    float rw = rois[r * 4 + 2], rh = rois[r * 4 + 3];
    float sx = __fdiv_rn(rw, 7.0f);
    float sy = __fdiv_rn(rh, 7.0f);
    int bx[8], by[8];
    #pragma unroll
    for (int k = 0; k < 8; k++) {
        bx[k] = (int)__fadd_rn(rx, __fmul_rn((float)k, sx));
        by[k] = (int)__fadd_rn(ry, __fmul_rn((float)k, sy));
        g_bx[r][k] = bx[k];
        g_by[r][k] = by[k];
    }
    g_bbox[r] = make_int4(bx[0], bx[7], by[0], by[7]);
}

// ---- kernel 2: tile sweep ------------------------------------------------
// CTA = (tile, channel-half). Stage 10x10 px x 256 ch (100 KB) into SMEM,
// then for every (roi,bin) rect intersecting this tile, max-reduce from SMEM
// and store a partial record. 2 CTAs/SM -> stage/compute overlap across CTAs.
__global__ __launch_bounds__(128) void tile_kernel(const float4* __restrict__ img4)
{
    extern __shared__ float4 smem[];            // [100 px][64 float4]
    const int tid   = threadIdx.x;
    const int chalf = blockIdx.x & 1;
    const int tile  = blockIdx.x >> 1;
    const int tx = tile % NTX, ty = tile / NTX;
    const int x0 = tx * TW,   y0 = ty * TH;

    // ---- stage: 6400 float4, perfectly coalesced, 50 iters/thread -------
    {
        const float4* __restrict__ src = img4 + chalf * 64;
        #pragma unroll 5
        for (int i = tid; i < TH * TW * 64; i += 128) {
            int p  = i >> 6;                    // pixel 0..99
            int c  = i & 63;                    // float4 within half
            int py = p / TW;
            int px = p - py * TW;
            smem[i] = src[((size_t)(y0 + py) * IMG_W + (x0 + px)) * C4 + c];
        }
    }
    __syncthreads();

    // thread owns 2 channels: float2 at pixel*128 + tid (pixel stride 128 f2)
    const float2* __restrict__ sm2 = (const float2*)smem;
    float2* __restrict__ part2 = (float2*)g_partial;

    #pragma unroll 1
    for (int r = 0; r < NROIS; r++) {
        int4 bb = g_bbox[r];                    // exact bbox test
        if (bb.x >= x0 + TW || bb.y <= x0 || bb.z >= y0 + TH || bb.w <= y0)
            continue;
        int bx[8], by[8];
        #pragma unroll
        for (int k = 0; k < 8; k++) { bx[k] = g_bx[r][k]; by[k] = g_by[r][k]; }

        #pragma unroll 1
        for (int jy = 0; jy < POOLP; jy++) {
            int rlo = max(by[jy],     y0);
            int rhi = min(by[jy + 1], y0 + TH);
            if (rlo >= rhi) continue;
            int sy = ty - by[jy] / TH;          // slot row 0/1
            #pragma unroll 1
            for (int ix = 0; ix < POOLP; ix++) {
                int clo = max(bx[ix],     x0);
                int chi = min(bx[ix + 1], x0 + TW);
                if (clo >= chi) continue;
                int sx = tx - bx[ix] / TW;      // slot col 0/1

                float2 m0 = make_float2(-CUDART_INF_F, -CUDART_INF_F);
                float2 m1 = m0;
                for (int y = rlo; y < rhi; y++) {
                    const float2* rowp =
                        sm2 + ((size_t)((y - y0) * TW + (clo - x0))) * 128 + tid;
                    int n = chi - clo;
                    int x = 0;
                    for (; x + 1 < n; x += 2) {  // 2 accumulators: break chain
                        float2 v0 = rowp[(size_t)x * 128];
                        float2 v1 = rowp[(size_t)(x + 1) * 128];
                        m0.x = fmaxf(m0.x, v0.x); m0.y = fmaxf(m0.y, v0.y);
                        m1.x = fmaxf(m1.x, v1.x); m1.y = fmaxf(m1.y, v1.y);
                    }
                    if (x < n) {
                        float2 v0 = rowp[(size_t)x * 128];
                        m0.x = fmaxf(m0.x, v0.x); m0.y = fmaxf(m0.y, v0.y);
                    }
                }
                m0.x = fmaxf(m0.x, m1.x); m0.y = fmaxf(m0.y, m1.y);

                int slot = ((r * NBINS + jy * POOLP + ix) * 2 + sy) * 2 + sx;
                part2[(size_t)slot * 256 + chalf * 128 + tid] = m0;
            }
        }
    }
}

// ---- kernel 3: combine <=4 tile partials per bin -------------------------
__global__ __launch_bounds__(128) void reduce_kernel(float4* __restrict__ out4)
{
    const int tid = threadIdx.x;
    const int bid = blockIdx.x;                 // r*49 + jy*7 + ix
    int r   = bid / NBINS;
    int bin = bid - r * NBINS;
    int jy  = bin / POOLP;
    int ix  = bin - jy * POOLP;

    int bx0 = g_bx[r][ix], bx1 = g_bx[r][ix + 1];
    int by0 = g_by[r][jy], by1 = g_by[r][jy + 1];
    int tx0 = bx0 / TW,    ty0 = by0 / TH;
    int ntx = min((bx1 - 1) / TW, NTX - 1) - tx0 + 1;   // 1 or 2
    int nty = min((by1 - 1) / TH, NTY - 1) - ty0 + 1;   // 1 or 2

    float4 m = make_float4(-CUDART_INF_F, -CUDART_INF_F,
                           -CUDART_INF_F, -CUDART_INF_F);
    int base = bid * 4;
    #pragma unroll 1
    for (int sy = 0; sy < nty; sy++)
        #pragma unroll 1
        for (int sx = 0; sx < ntx; sx++) {
            float4 v = g_partial[(size_t)(base + sy * 2 + sx) * C4 + tid];
            m.x = fmaxf(m.x, v.x); m.y = fmaxf(m.y, v.y);
            m.z = fmaxf(m.z, v.z); m.w = fmaxf(m.w, v.w);
        }
    out4[(size_t)bid * C4 + tid] = m;
}

// ---- launch --------------------------------------------------------------
extern "C" void kernel_launch(void* const* d_in, const int* in_sizes, int n_in,
                              void* d_out, int out_size)
{
    const float* img  = (const float*)d_in[0];
    const float* rois = (const float*)d_in[1];
    float4* out = (float4*)d_out;

    const int smem_bytes = TH * TW * 64 * (int)sizeof(float4);  // 102400
    cudaFuncSetAttribute(tile_kernel,
                         cudaFuncAttributeMaxDynamicSharedMemorySize, smem_bytes);

    prep_kernel<<<1, NROIS>>>(rois);
    tile_kernel<<<NTX * NTY * 2, 128, smem_bytes>>>((const float4*)img);
    reduce_kernel<<<NROIS * NBINS, 128>>>(out);
}

// round 7
// speedup vs baseline: 1.6569x; 1.6569x over previous
#include <cuda_runtime.h>
#include <math_constants.h>

typedef unsigned int u32;

// img (1,200,200,512) f32 NHWC, rois (1,128,4) f32 (x,y,w,h), pool 7x7
// out (1,128,7,7,512) f32.
#define IMG_H 200
#define IMG_W 200
#define IMG_C 512
#define C4    128               // float4 per pixel record
#define POOLP 7
#define NROIS 128
#define NBINS 49
#define NBIN_TOT (NROIS * NBINS)   // 6272

#define TW 20
#define TH 20
#define NTX 10
#define NTY 10

#define NCHUNK 16               // channel chunks per tile
#define CH4    8                // float4 per chunk (32 channels)

#define LIST_CAP 2048           // worklist capacity per tile (16x margin vs ~125 expected)

// ---- device scratch (static: allocation-free) ----------------------------
__device__ u32      g_rect[NBIN_TOT];   // per-bin (bx0,bx1,by0,by1) packed bytes
__device__ int4     g_bbox[NROIS];      // (bx0, bx7, by0, by7)
// Partial maxima for bins spanning >1 tile: [bin][sy*2+sx][128 float4].
// Only written subslots are ever read -> no init needed.
__device__ float4   g_partial[(size_t)NBIN_TOT * 4 * C4];   // 51.4 MB

// ---- kernel 1: exact bin boundaries (JAX f32 op order, no fma) -----------
__global__ __launch_bounds__(NROIS) void prep_kernel(const float* __restrict__ rois)
{
    int r = threadIdx.x;
    float rx = rois[r * 4 + 0], ry = rois[r * 4 + 1];
    float rw = rois[r * 4 + 2], rh = rois[r * 4 + 3];
    float sx = __fdiv_rn(rw, 7.0f);
    float sy = __fdiv_rn(rh, 7.0f);
    int bx[8], by[8];
    #pragma unroll
    for (int k = 0; k < 8; k++) {
        bx[k] = (int)__fadd_rn(rx, __fmul_rn((float)k, sx));
        by[k] = (int)__fadd_rn(ry, __fmul_rn((float)k, sy));
    }
    g_bbox[r] = make_int4(bx[0], bx[7], by[0], by[7]);
    #pragma unroll
    for (int jy = 0; jy < POOLP; jy++)
        #pragma unroll
        for (int ix = 0; ix < POOLP; ix++)
            g_rect[r * NBINS + jy * POOLP + ix] =
                (u32)bx[ix] | ((u32)bx[ix + 1] << 8) |
                ((u32)by[jy] << 16) | ((u32)by[jy + 1] << 24);
}

// ---- kernel 2: tile sweep ------------------------------------------------
// CTA = (20x20 px tile, 32-channel chunk). Stage tile slab (51.2 KB) into
// SMEM, build the (roi,bin)-rect worklist in parallel, then 8-lane groups
// drain entries from SMEM. Single-tile bins write out directly; split bins
// write partial slots.
__global__ __launch_bounds__(256) void tile_kernel(const float4* __restrict__ img4,
                                                   float4* __restrict__ out4)
{
    extern __shared__ float4 smem[];
    float4* tilebuf = smem;                                  // 3200 float4
    uint2*  list    = (uint2*)(smem + TH * TW * CH4);        // LIST_CAP
    int*    cnt     = (int*)(list + LIST_CAP);

    const int tid   = threadIdx.x;
    const int chunk = blockIdx.x & (NCHUNK - 1);
    const int tile  = blockIdx.x >> 4;
    const int tx = tile % NTX, ty = tile / NTX;
    const int x0 = tx * TW,    y0 = ty * TH;

    if (tid == 0) *cnt = 0;
    __syncthreads();

    // -- build worklist: one thread per ROI (parallel, cheap) --------------
    if (tid < NROIS) {
        int4 bb = g_bbox[tid];
        if (bb.x < x0 + TW && bb.y > x0 && bb.z < y0 + TH && bb.w > y0) {
            for (int b = 0; b < NBINS; b++) {
                u32 rc = g_rect[tid * NBINS + b];
                int bx0 = rc & 255, bx1 = (rc >> 8) & 255;
                int by0 = (rc >> 16) & 255, by1 = rc >> 24;
                int cl = max(bx0 - x0, 0), ch = min(bx1 - x0, TW);
                int rl = max(by0 - y0, 0), rh = min(by1 - y0, TH);
                if (cl < ch && rl < rh) {
                    int tx0 = bx0 / TW, ty0 = by0 / TH;
                    int bid = tid * NBINS + b;
                    u32 dst;
                    if (tx0 == (bx1 - 1) / TW && ty0 == (by1 - 1) / TH)
                        dst = (u32)bid | 0x80000000u;            // direct to out
                    else
                        dst = (u32)(bid * 4 + (ty - ty0) * 2 + (tx - tx0));
                    int idx = atomicAdd(cnt, 1);
                    if (idx < LIST_CAP)
                        list[idx] = make_uint2(
                            (u32)rl | ((u32)rh << 5) |
                            ((u32)cl << 10) | ((u32)ch << 15), dst);
                }
            }
        }
    }

    // -- stage tile slab: 3200 float4, coalesced ---------------------------
    {
        const float4* __restrict__ src = img4 + chunk * CH4;
        #pragma unroll
        for (int i = tid; i < TH * TW * CH4; i += 256) {
            int p = i >> 3;                 // pixel 0..399
            int c = i & 7;
            int py = p / TW;
            int px = p - py * TW;
            tilebuf[i] = src[((y0 + py) * IMG_W + (x0 + px)) * C4 + c];
        }
    }
    __syncthreads();

    // -- sweep: 32 groups of 8 lanes, group per entry ----------------------
    const int g = tid >> 3, lane = tid & 7;
    const int n = min(*cnt, LIST_CAP);
    for (int e = g; e < n; e += 32) {
        uint2 en = list[e];
        int rl = en.x & 31, rh = (en.x >> 5) & 31;
        int cl = (en.x >> 10) & 31, ch = (en.x >> 15) & 31;

        float4 m0 = make_float4(-CUDART_INF_F, -CUDART_INF_F,
                                -CUDART_INF_F, -CUDART_INF_F);
        float4 m1 = m0;
        for (int y = rl; y < rh; y++) {
            const float4* rp = tilebuf + (y * TW + cl) * CH4 + lane;
            int nx = ch - cl;
            int x = 0;
            for (; x + 1 < nx; x += 2) {            // 2 accumulators
                float4 v0 = rp[x * CH4];
                float4 v1 = rp[(x + 1) * CH4];
                m0.x = fmaxf(m0.x, v0.x); m0.y = fmaxf(m0.y, v0.y);
                m0.z = fmaxf(m0.z, v0.z); m0.w = fmaxf(m0.w, v0.w);
                m1.x = fmaxf(m1.x, v1.x); m1.y = fmaxf(m1.y, v1.y);
                m1.z = fmaxf(m1.z, v1.z); m1.w = fmaxf(m1.w, v1.w);
            }
            if (x < nx) {
                float4 v0 = rp[x * CH4];
                m0.x = fmaxf(m0.x, v0.x); m0.y = fmaxf(m0.y, v0.y);
                m0.z = fmaxf(m0.z, v0.z); m0.w = fmaxf(m0.w, v0.w);
            }
        }
        m0.x = fmaxf(m0.x, m1.x); m0.y = fmaxf(m0.y, m1.y);
        m0.z = fmaxf(m0.z, m1.z); m0.w = fmaxf(m0.w, m1.w);

        float4* dst = (en.y & 0x80000000u)
                    ? out4 + (size_t)(en.y & 0x7fffffffu) * C4
                    : g_partial + (size_t)en.y * C4;
        dst[chunk * CH4 + lane] = m0;
    }
}

// ---- kernel 3: combine split-bin partials --------------------------------
__global__ __launch_bounds__(128) void reduce_kernel(float4* __restrict__ out4)
{
    const int bid = blockIdx.x;
    u32 rc = g_rect[bid];
    int bx0 = rc & 255, bx1 = (rc >> 8) & 255;
    int by0 = (rc >> 16) & 255, by1 = rc >> 24;
    int ntx = (bx1 - 1) / TW - bx0 / TW + 1;   // 1 or 2
    int nty = (by1 - 1) / TH - by0 / TH + 1;   // 1 or 2
    if (ntx == 1 && nty == 1) return;          // tile kernel wrote out directly

    const int tid = threadIdx.x;
    float4 m = make_float4(-CUDART_INF_F, -CUDART_INF_F,
                           -CUDART_INF_F, -CUDART_INF_F);
    #pragma unroll 1
    for (int sy = 0; sy < nty; sy++)
        #pragma unroll 1
        for (int sx = 0; sx < ntx; sx++) {
            float4 v = g_partial[(size_t)(bid * 4 + sy * 2 + sx) * C4 + tid];
            m.x = fmaxf(m.x, v.x); m.y = fmaxf(m.y, v.y);
            m.z = fmaxf(m.z, v.z); m.w = fmaxf(m.w, v.w);
        }
    out4[(size_t)bid * C4 + tid] = m;
}

// ---- launch --------------------------------------------------------------
extern "C" void kernel_launch(void* const* d_in, const int* in_sizes, int n_in,
                              void* d_out, int out_size)
{
    const float* img  = (const float*)d_in[0];
    const float* rois = (const float*)d_in[1];
    float4* out = (float4*)d_out;

    const int smem_bytes = TH * TW * CH4 * (int)sizeof(float4)   // 51200
                         + LIST_CAP * (int)sizeof(uint2)         // 16384
                         + 128;                                  // count + pad
    cudaFuncSetAttribute(tile_kernel,
                         cudaFuncAttributeMaxDynamicSharedMemorySize, smem_bytes);

    prep_kernel<<<1, NROIS>>>(rois);
    tile_kernel<<<NTX * NTY * NCHUNK, 256, smem_bytes>>>((const float4*)img, out);
    reduce_kernel<<<NBIN_TOT, 128>>>(out);
}

// round 8
// speedup vs baseline: 2.2234x; 1.3419x over previous
#include <cuda_runtime.h>
#include <math_constants.h>

typedef unsigned int u32;

// img (1,200,200,512) f32 NHWC, rois (1,128,4) f32 (x,y,w,h), pool 7x7
// out (1,128,7,7,512) f32.
#define IMG_H 200
#define IMG_W 200
#define IMG_C 512
#define C4    128               // float4 per pixel record
#define POOLP 7
#define NROIS 128
#define NBINS 49
#define NBIN_TOT (NROIS * NBINS)   // 6272

#define TW 20
#define TH 20
#define NTX 10
#define NTY 10
#define NTILES (NTX * NTY)      // 100

#define NCHUNK 16               // channel chunks per tile
#define CH4    8                // float4 per chunk (32 channels)

// Provable per-tile worst case: every (roi,bin) contributes at most ONE entry
// to a given tile => cap = 128*49 = 6272. No overflow possible.
#define TLIST_CAP NBIN_TOT

// ---- device scratch (static: allocation-free) ----------------------------
__device__ u32    g_rect[NBIN_TOT];          // per-bin (bx0,bx1,by0,by1) packed
__device__ int    g_listcnt[NTILES];
__device__ uint2  g_list[NTILES][TLIST_CAP]; // 5.0 MB
// Partial maxima for bins spanning >1 tile: [bin][sy*2+sx][128 float4].
// Only written subslots are ever read -> no init needed.
__device__ float4 g_partial[(size_t)NBIN_TOT * 4 * C4];   // 51.4 MB

// ---- kernel 1: exact bin boundaries + per-tile worklists -----------------
// Boundary math must match JAX f32 op order exactly: step = w/7;
// b[k] = int(x + k*step), mul then add, NO fma contraction.
__global__ __launch_bounds__(NROIS) void prep_kernel(const float* __restrict__ rois)
{
    __shared__ int s_cnt[NTILES];
    const int r = threadIdx.x;
    if (r < NTILES) s_cnt[r] = 0;
    __syncthreads();

    float rx = rois[r * 4 + 0], ry = rois[r * 4 + 1];
    float rw = rois[r * 4 + 2], rh = rois[r * 4 + 3];
    float sx = __fdiv_rn(rw, 7.0f);
    float sy = __fdiv_rn(rh, 7.0f);
    int bx[8], by[8];
    #pragma unroll
    for (int k = 0; k < 8; k++) {
        bx[k] = (int)__fadd_rn(rx, __fmul_rn((float)k, sx));
        by[k] = (int)__fadd_rn(ry, __fmul_rn((float)k, sy));
    }

    #pragma unroll 1
    for (int jy = 0; jy < POOLP; jy++) {
        int ry0 = by[jy], ry1 = by[jy + 1];
        int ty0 = ry0 / TH, ty1 = (ry1 - 1) / TH;
        #pragma unroll 1
        for (int ix = 0; ix < POOLP; ix++) {
            int rx0 = bx[ix], rx1 = bx[ix + 1];
            int tx0 = rx0 / TW, tx1 = (rx1 - 1) / TW;
            int bid = r * NBINS + jy * POOLP + ix;
            g_rect[bid] = (u32)rx0 | ((u32)rx1 << 8) |
                          ((u32)ry0 << 16) | ((u32)ry1 << 24);
            bool single = (tx0 == tx1) && (ty0 == ty1);
            for (int tyy = ty0; tyy <= ty1; tyy++) {
                int rl = max(ry0 - tyy * TH, 0);
                int rhh = min(ry1 - tyy * TH, TH);
                for (int txx = tx0; txx <= tx1; txx++) {
                    int cl = max(rx0 - txx * TW, 0);
                    int chh = min(rx1 - txx * TW, TW);
                    u32 dst = single ? ((u32)bid | 0x80000000u)
                        : (u32)(bid * 4 + (tyy - ty0) * 2 + (txx - tx0));
                    int tile = tyy * NTX + txx;
                    int idx = atomicAdd(&s_cnt[tile], 1);
                    g_list[tile][idx] = make_uint2(
                        (u32)rl | ((u32)rhh << 5) |
                        ((u32)cl << 10) | ((u32)chh << 15), dst);
                }
            }
        }
    }
    __syncthreads();
    if (r < NTILES) g_listcnt[r] = s_cnt[r];
}

// ---- kernel 2: tile sweep ------------------------------------------------
// CTA = (20x20 px tile, 32-channel chunk). Stage slab (51.2 KB) into SMEM,
// then 32 groups of 8 lanes drain the PREBUILT worklist. No atomics, no bin
// scan, one sync. 4 CTAs/SM.
__global__ __launch_bounds__(256, 4) void tile_kernel(const float4* __restrict__ img4,
                                                      float4* __restrict__ out4)
{
    extern __shared__ float4 tilebuf[];          // 3200 float4

    const int tid   = threadIdx.x;
    const int chunk = blockIdx.x & (NCHUNK - 1);
    const int tile  = blockIdx.x >> 4;
    const int tx = tile % NTX, ty = tile / NTX;
    const int x0 = tx * TW,    y0 = ty * TH;

    // -- stage slab: 3200 float4, coalesced --------------------------------
    {
        const float4* __restrict__ src = img4 + chunk * CH4;
        #pragma unroll
        for (int i = tid; i < TH * TW * CH4; i += 256) {
            int p = i >> 3;                      // pixel 0..399
            int c = i & 7;
            int py = p / TW;
            int px = p - py * TW;
            tilebuf[i] = src[((y0 + py) * IMG_W + (x0 + px)) * C4 + c];
        }
    }
    const int n = g_listcnt[tile];
    const uint2* __restrict__ lst = g_list[tile];
    __syncthreads();

    // -- sweep: group of 8 lanes per entry ---------------------------------
    const int g = tid >> 3, lane = tid & 7;
    for (int e = g; e < n; e += 32) {
        uint2 en = __ldg(&lst[e]);
        int rl = en.x & 31, rh = (en.x >> 5) & 31;
        int cl = (en.x >> 10) & 31, ch = (en.x >> 15) & 31;

        float4 m0 = make_float4(-CUDART_INF_F, -CUDART_INF_F,
                                -CUDART_INF_F, -CUDART_INF_F);
        float4 m1 = m0;
        for (int y = rl; y < rh; y++) {
            const float4* rp = tilebuf + (y * TW + cl) * CH4 + lane;
            int nx = ch - cl;
            int x = 0;
            for (; x + 1 < nx; x += 2) {         // 2 accumulators
                float4 v0 = rp[x * CH4];
                float4 v1 = rp[(x + 1) * CH4];
                m0.x = fmaxf(m0.x, v0.x); m0.y = fmaxf(m0.y, v0.y);
                m0.z = fmaxf(m0.z, v0.z); m0.w = fmaxf(m0.w, v0.w);
                m1.x = fmaxf(m1.x, v1.x); m1.y = fmaxf(m1.y, v1.y);
                m1.z = fmaxf(m1.z, v1.z); m1.w = fmaxf(m1.w, v1.w);
            }
            if (x < nx) {
                float4 v0 = rp[x * CH4];
                m0.x = fmaxf(m0.x, v0.x); m0.y = fmaxf(m0.y, v0.y);
                m0.z = fmaxf(m0.z, v0.z); m0.w = fmaxf(m0.w, v0.w);
            }
        }
        m0.x = fmaxf(m0.x, m1.x); m0.y = fmaxf(m0.y, m1.y);
        m0.z = fmaxf(m0.z, m1.z); m0.w = fmaxf(m0.w, m1.w);

        float4* dst = (en.y & 0x80000000u)
                    ? out4 + (size_t)(en.y & 0x7fffffffu) * C4
                    : g_partial + (size_t)en.y * C4;
        dst[chunk * CH4 + lane] = m0;
    }
}

// ---- kernel 3: combine split-bin partials --------------------------------
__global__ __launch_bounds__(128) void reduce_kernel(float4* __restrict__ out4)
{
    const int bid = blockIdx.x;
    u32 rc = g_rect[bid];
    int bx0 = rc & 255, bx1 = (rc >> 8) & 255;
    int by0 = (rc >> 16) & 255, by1 = rc >> 24;
    int ntx = (bx1 - 1) / TW - bx0 / TW + 1;   // 1 or 2
    int nty = (by1 - 1) / TH - by0 / TH + 1;   // 1 or 2
    if (ntx == 1 && nty == 1) return;          // tile kernel wrote out directly

    const int tid = threadIdx.x;
    float4 m = make_float4(-CUDART_INF_F, -CUDART_INF_F,
                           -CUDART_INF_F, -CUDART_INF_F);
    #pragma unroll 1
    for (int sy = 0; sy < nty; sy++)
        #pragma unroll 1
        for (int sx = 0; sx < ntx; sx++) {
            float4 v = g_partial[(size_t)(bid * 4 + sy * 2 + sx) * C4 + tid];
            m.x = fmaxf(m.x, v.x); m.y = fmaxf(m.y, v.y);
            m.z = fmaxf(m.z, v.z); m.w = fmaxf(m.w, v.w);
        }
    out4[(size_t)bid * C4 + tid] = m;
}

// ---- launch --------------------------------------------------------------
extern "C" void kernel_launch(void* const* d_in, const int* in_sizes, int n_in,
                              void* d_out, int out_size)
{
    const float* img  = (const float*)d_in[0];
    const float* rois = (const float*)d_in[1];
    float4* out = (float4*)d_out;

    const int smem_bytes = TH * TW * CH4 * (int)sizeof(float4);  // 51200
    cudaFuncSetAttribute(tile_kernel,
                         cudaFuncAttributeMaxDynamicSharedMemorySize, smem_bytes);

    prep_kernel<<<1, NROIS>>>(rois);
    tile_kernel<<<NTILES * NCHUNK, 256, smem_bytes>>>((const float4*)img, out);
    reduce_kernel<<<NBIN_TOT, 128>>>(out);
}